// round 11
// baseline (speedup 1.0000x reference)
#include <cuda_runtime.h>
#include <cuda_bf16.h>
#include <math.h>

typedef unsigned long long ull;

// ---------------- problem constants ------------------------------------------
#define NQ      64
#define KDIM    768
#define TILE_M  128                 // bank rows per CTA tile
#define CHUNK_K 64                  // fp32 k-elems per chunk
#define NCHUNK  (KDIM / CHUNK_K)    // 12
#define MAXROWS 500000
#define NSEG    8                   // top-k segments per query
#define SEGK    16                  // candidates kept per (q, segment)
#define CAND    32                  // candidates exactly rescored per query
#define TB_PAD  136                 // transpose buffer row pitch (bf16 elems)

// ---------------- smem layout (score kernel) ---------------------------------
#define SM_INVN 0                                   // float[128]
#define SM_QD   1024                                // [64k][128] f32 q-duplicated = 32 KB
#define SM_BT   (SM_QD + CHUNK_K * 128 * 4)         // 33792: [64k][128] f32 bankT = 32 KB
#define SCORE_SMEM (SM_BT + CHUNK_K * 128 * 4)      // 66560

// ---------------- device scratch (allocation-free rule) ----------------------
__device__ __align__(16) float g_qn  [NQ * KDIM];          // fp32 normalized queries [q][k]
__device__ __align__(16) float g_qnT2[KDIM * 2 * NQ];      // transposed+duplicated [k][2q]
__device__ __align__(16) __nv_bfloat16 g_simsb[(size_t)NQ * MAXROWS]; // 64 MB bf16 sims
__device__ float g_segv[NQ * NSEG * SEGK];
__device__ int   g_segi[NQ * NSEG * SEGK];

// ---------------- f32x2 packed FMA (FFMA2) -----------------------------------
__device__ __forceinline__ void ffma2(ull& d, ull a, ull b) {
    asm("fma.rn.f32x2 %0, %1, %2, %0;" : "+l"(d) : "l"(a), "l"(b));
}
__device__ __forceinline__ void unpack2(float& lo, float& hi, ull v) {
    asm("mov.b64 {%0, %1}, %2;" : "=f"(lo), "=f"(hi) : "l"(v));
}

// ---------------- kernel 1: normalize queries + build transposed dup copy ----
__global__ void norm_q_kernel(const float* __restrict__ q) {
    __shared__ float red[256];
    const int qi = blockIdx.x, tid = threadIdx.x;
    const int KW = KDIM / 4;  // 192
    float4 f = make_float4(0.f, 0.f, 0.f, 0.f);
    if (tid < KW) f = *(const float4*)(q + qi * KDIM + tid * 4);
    red[tid] = f.x * f.x + f.y * f.y + f.z * f.z + f.w * f.w;
    __syncthreads();
    for (int st = 128; st > 0; st >>= 1) {
        if (tid < st) red[tid] += red[tid + st];
        __syncthreads();
    }
    const float inv = 1.0f / fmaxf(sqrtf(red[0]), 1e-12f);
    if (tid < KW) {
        float4 o = make_float4(f.x * inv, f.y * inv, f.z * inv, f.w * inv);
        *(float4*)(g_qn + qi * KDIM + tid * 4) = o;
        const float v[4] = {o.x, o.y, o.z, o.w};
        #pragma unroll
        for (int j = 0; j < 4; j++) {
            const int k = tid * 4 + j;
            g_qnT2[k * (2 * NQ) + qi * 2    ] = v[j];
            g_qnT2[k * (2 * NQ) + qi * 2 + 1] = v[j];
        }
    }
}

// ---------------- kernel 2: f32x2 GEMM score ---------------------------------
__device__ __forceinline__ void ld_bank(float4 (&f)[8], const float* const (&rp)[8],
                                        const bool (&vld)[8], int c) {
    #pragma unroll
    for (int p = 0; p < 8; p++) {
        if (vld[p]) f[p] = *(const float4*)(rp[p] + c * CHUNK_K);
        else        f[p] = make_float4(0.f, 0.f, 0.f, 0.f);
    }
}
__device__ __forceinline__ void ld_q(float4 (&qv)[8], const float* qsrc) {
    #pragma unroll
    for (int i = 0; i < 8; i++) qv[i] = *(const float4*)(qsrc + i * 4);
}

__global__ __launch_bounds__(256, 2)
void score_kernel(const float* __restrict__ bank, int nrows) {
    extern __shared__ char smem[];
    float* invn = (float*)(smem + SM_INVN);
    float* QDf  = (float*)(smem + SM_QD);
    float* BTf  = (float*)(smem + SM_BT);
    ull*   QD   = (ull*)QDf;          // [k][64] (q,q) pairs
    ull*   BT   = (ull*)BTf;          // [k][64] row pairs (swizzled)
    const int tid = threadIdx.x, warp = tid >> 5, lane = tid & 31;
    const int lr = lane >> 4, lc = lane & 15;

    // ---- gmem bank mapping: 16 lanes per row, line-contiguous LDG.128 --------
    int rloc[8]; const float* rp[8]; bool vld[8]; float ssq[8];
    #pragma unroll
    for (int p = 0; p < 8; p++) {
        int r = p * 16 + warp * 2 + lr;
        rloc[p] = r;
        long long grow = (long long)blockIdx.x * TILE_M + r;
        vld[p] = grow < (long long)nrows;
        rp[p]  = bank + grow * (long long)KDIM + lc * 4;
        ssq[p] = 0.f;
    }
    const int bswz = (lc & 7) << 2;          // fp32-col XOR swizzle ((k>>2)&7)<<2, k>>2==lc

    // ---- q-chunk staging mapping (straight copy, 32 floats/thread) -----------
    const int qoff = tid * 32;

    // ---- compute mapping: 4 row-pairs (stride 16) x 4 queries -----------------
    const int mbase = tid & 15;
    const int q0    = (tid >> 4) * 4;

    ull acc[4][4];
    #pragma unroll
    for (int i = 0; i < 4; i++)
        #pragma unroll
        for (int j = 0; j < 4; j++) acc[i][j] = 0ull;   // (0.f, 0.f)

    float4 f[8], qv[8];
    ld_bank(f, rp, vld, 0);
    ld_q(qv, g_qnT2 + qoff);

    for (int c = 0; c < NCHUNK; c++) {
        // stage bank chunk (transposed, swizzled) + accumulate row sumsq
        #pragma unroll
        for (int p = 0; p < 8; p++) {
            float4 fv = f[p];
            ssq[p] += fv.x * fv.x + fv.y * fv.y + fv.z * fv.z + fv.w * fv.w;
            const int pc = rloc[p] ^ bswz;
            BTf[(lc * 4 + 0) * 128 + pc] = fv.x;
            BTf[(lc * 4 + 1) * 128 + pc] = fv.y;
            BTf[(lc * 4 + 2) * 128 + pc] = fv.z;
            BTf[(lc * 4 + 3) * 128 + pc] = fv.w;
        }
        // stage q chunk (straight copy of duplicated-transposed slice)
        #pragma unroll
        for (int i = 0; i < 8; i++)
            *(float4*)&QDf[qoff + i * 4] = qv[i];
        __syncthreads();

        // prefetch next chunk while computing this one
        if (c + 1 < NCHUNK) {
            ld_bank(f, rp, vld, c + 1);
            ld_q(qv, g_qnT2 + (c + 1) * (CHUNK_K * 128) + qoff);
        }

        // f32x2 GEMM over 64 k
        #pragma unroll
        for (int t = 0; t < 16; t++) {
            const int swp = (t & 7) << 1;    // pair-index swizzle
            const int pm0 = (mbase     ) ^ swp;
            const int pm1 = (mbase + 16) ^ swp;
            const int pm2 = (mbase + 32) ^ swp;
            const int pm3 = (mbase + 48) ^ swp;
            #pragma unroll
            for (int kk = 0; kk < 4; kk++) {
                const int kb = (t * 4 + kk) * 64;
                ull b0 = BT[kb + pm0];
                ull b1 = BT[kb + pm1];
                ull b2 = BT[kb + pm2];
                ull b3 = BT[kb + pm3];
                ull qa = QD[kb + q0    ];
                ull qb = QD[kb + q0 + 1];
                ull qc = QD[kb + q0 + 2];
                ull qd = QD[kb + q0 + 3];
                ffma2(acc[0][0], b0, qa); ffma2(acc[0][1], b0, qb);
                ffma2(acc[0][2], b0, qc); ffma2(acc[0][3], b0, qd);
                ffma2(acc[1][0], b1, qa); ffma2(acc[1][1], b1, qb);
                ffma2(acc[1][2], b1, qc); ffma2(acc[1][3], b1, qd);
                ffma2(acc[2][0], b2, qa); ffma2(acc[2][1], b2, qb);
                ffma2(acc[2][2], b2, qc); ffma2(acc[2][3], b2, qd);
                ffma2(acc[3][0], b3, qa); ffma2(acc[3][1], b3, qb);
                ffma2(acc[3][2], b3, qc); ffma2(acc[3][3], b3, qd);
            }
        }
        __syncthreads();
    }

    // ---- row inverse norms (16 lanes share a row) -----------------------------
    #pragma unroll
    for (int p = 0; p < 8; p++) {
        float s = ssq[p];
        s += __shfl_xor_sync(0xffffffffu, s, 1);
        s += __shfl_xor_sync(0xffffffffu, s, 2);
        s += __shfl_xor_sync(0xffffffffu, s, 4);
        s += __shfl_xor_sync(0xffffffffu, s, 8);
        if (lc == 0) invn[rloc[p]] = 1.0f / fmaxf(sqrtf(s), 1e-12f);
    }
    __syncthreads();

    // ---- epilogue 1: accs -> smem transpose buffer [q][TB_PAD] bf16 -----------
    {
        __nv_bfloat16* tb = (__nv_bfloat16*)(smem + SM_QD);
        #pragma unroll
        for (int i = 0; i < 4; i++) {
            const int r0 = (mbase + 16 * i) * 2;
            const float i0 = invn[r0], i1 = invn[r0 + 1];
            #pragma unroll
            for (int j = 0; j < 4; j++) {
                float lo, hi;
                unpack2(lo, hi, acc[i][j]);
                __nv_bfloat162 v = __floats2bfloat162_rn(lo * i0, hi * i1);
                *(__nv_bfloat162*)&tb[(q0 + j) * TB_PAD + r0] = v;
            }
        }
    }
    __syncthreads();

    // ---- epilogue 2: coalesced vectorized sims store --------------------------
    {
        const int q = tid >> 2, seg = tid & 3;
        const long long tb0 = (long long)blockIdx.x * TILE_M;
        const __nv_bfloat16* tb = (const __nv_bfloat16*)(smem + SM_QD);
        __nv_bfloat16* dst = g_simsb + (size_t)q * nrows;
        if ((nrows & 7) == 0) {
            #pragma unroll
            for (int i = 0; i < 4; i++) {
                long long g0 = tb0 + seg * 32 + i * 8;
                if (g0 + 8 <= (long long)nrows) {
                    uint4 v = *(const uint4*)(smem + SM_QD + q * (TB_PAD * 2) + seg * 64 + i * 16);
                    *(uint4*)(dst + g0) = v;
                } else {
                    for (int e = 0; e < 8 && g0 + e < (long long)nrows; e++)
                        dst[g0 + e] = tb[q * TB_PAD + seg * 32 + i * 8 + e];
                }
            }
        } else {
            for (int i = 0; i < 32; i++) {
                long long g0 = tb0 + seg * 32 + i;
                if (g0 < (long long)nrows) dst[g0] = tb[q * TB_PAD + seg * 32 + i];
            }
        }
    }
}

// ---------------- kernel 3: segmented top-16 screening -----------------------
__device__ __forceinline__ void tk_insert(float (&v)[SEGK], int (&id)[SEGK],
                                          float nv, int ni) {
    if (nv <= v[SEGK - 1]) return;
    int j = SEGK - 1;
    while (j > 0 && nv > v[j - 1]) { v[j] = v[j - 1]; id[j] = id[j - 1]; j--; }
    v[j] = nv; id[j] = ni;
}

__global__ __launch_bounds__(256, 1) void topk_kernel(int nrows) {
    __shared__ float sv[256 * SEGK];
    __shared__ int   si[256 * SEGK];
    const int seg = blockIdx.x, q = blockIdx.y, tid = threadIdx.x;
    const int len  = ((nrows + NSEG - 1) / NSEG + 3) & ~3;
    const int base = seg * len;
    const int end  = min(base + len, nrows);
    const __nv_bfloat16* s = g_simsb + (size_t)q * nrows;

    float vals[SEGK]; int ids[SEGK];
    #pragma unroll
    for (int i = 0; i < SEGK; i++) { vals[i] = -3.4e38f; ids[i] = 0x7fffffff; }

    if ((nrows & 3) == 0 && base < end) {
        const uint2* s4 = (const uint2*)s;
        for (int i = (base >> 2) + tid; i < (end >> 2); i += 256) {
            uint2 u = s4[i];
            __nv_bfloat162 p0 = *(__nv_bfloat162*)&u.x;
            __nv_bfloat162 p1 = *(__nv_bfloat162*)&u.y;
            int bi = i << 2;
            tk_insert(vals, ids, __low2float(p0),  bi);
            tk_insert(vals, ids, __high2float(p0), bi + 1);
            tk_insert(vals, ids, __low2float(p1),  bi + 2);
            tk_insert(vals, ids, __high2float(p1), bi + 3);
        }
    } else {
        for (int i = base + tid; i < end; i += 256)
            tk_insert(vals, ids, __bfloat162float(s[i]), i);
    }

    #pragma unroll
    for (int i = 0; i < SEGK; i++) { sv[tid * SEGK + i] = vals[i]; si[tid * SEGK + i] = ids[i]; }
    __syncthreads();

    for (int st = 128; st > 0; st >>= 1) {
        if (tid < st) {
            const int ao = tid * SEGK, bo = (tid + st) * SEGK;
            float ov[SEGK]; int oi[SEGK];
            int ia = 0, ib = 0;
            #pragma unroll
            for (int o = 0; o < SEGK; o++) {
                float va = (ia < SEGK) ? sv[ao + ia] : -3.4e38f;
                float vb = (ib < SEGK) ? sv[bo + ib] : -3.4e38f;
                bool takeA;
                if (va > vb) takeA = true;
                else if (va < vb) takeA = false;
                else takeA = (si[ao + min(ia, SEGK - 1)] <= si[bo + min(ib, SEGK - 1)]);
                if (takeA) { ov[o] = va; oi[o] = si[ao + min(ia, SEGK - 1)]; ia++; }
                else       { ov[o] = vb; oi[o] = si[bo + min(ib, SEGK - 1)]; ib++; }
            }
            #pragma unroll
            for (int o = 0; o < SEGK; o++) { sv[ao + o] = ov[o]; si[ao + o] = oi[o]; }
        }
        __syncthreads();
    }

    if (tid == 0) {
        #pragma unroll
        for (int i = 0; i < SEGK; i++) {
            g_segv[(q * NSEG + seg) * SEGK + i] = sv[i];
            g_segi[(q * NSEG + seg) * SEGK + i] = si[i];
        }
    }
}

// ---------------- kernel 4: merge + exact fp32 rescore + final top-k ---------
__global__ __launch_bounds__(256, 1)
void final_kernel(const float* __restrict__ bank, float* __restrict__ out,
                  int nrows, int k) {
    __shared__ float cv[NSEG * SEGK];
    __shared__ int   ci[NSEG * SEGK];
    __shared__ float sv[CAND];
    __shared__ int   sid[CAND];
    __shared__ float rv[CAND];
    const int q = blockIdx.x, tid = threadIdx.x;
    const int lane = tid & 31, warp = tid >> 5;

    if (tid < NSEG * SEGK) {
        cv[tid] = g_segv[q * NSEG * SEGK + tid];
        ci[tid] = g_segi[q * NSEG * SEGK + tid];
    }
    __syncthreads();

    if (tid == 0) {
        float bv[CAND]; int bi[CAND];
        #pragma unroll
        for (int i = 0; i < CAND; i++) { bv[i] = -3.4e38f; bi[i] = 0x7fffffff; }
        for (int i = 0; i < NSEG * SEGK; i++) {
            float v = cv[i]; int id = ci[i];
            float lv = bv[CAND - 1]; int li = bi[CAND - 1];
            if (v < lv || (v == lv && id >= li)) continue;
            int j = CAND - 1;
            while (j > 0 && (v > bv[j - 1] || (v == bv[j - 1] && id < bi[j - 1]))) {
                bv[j] = bv[j - 1]; bi[j] = bi[j - 1]; j--;
            }
            bv[j] = v; bi[j] = id;
        }
        #pragma unroll
        for (int i = 0; i < CAND; i++) { sv[i] = bv[i]; sid[i] = bi[i]; }
    }
    __syncthreads();

    for (int c = warp; c < CAND; c += 8) {
        const int id = sid[c];
        float val = -3.4e38f;
        if (id < nrows) {
            const float4* b4 = (const float4*)(bank + (long long)id * KDIM);
            const float4* q4 = (const float4*)(g_qn + q * KDIM);
            float dot = 0.f, ss = 0.f;
            #pragma unroll
            for (int i = 0; i < 6; i++) {
                float4 bb = b4[lane + i * 32];
                float4 qq = q4[lane + i * 32];
                dot = fmaf(qq.x, bb.x, fmaf(qq.y, bb.y, fmaf(qq.z, bb.z, fmaf(qq.w, bb.w, dot))));
                ss  = fmaf(bb.x, bb.x, fmaf(bb.y, bb.y, fmaf(bb.z, bb.z, fmaf(bb.w, bb.w, ss))));
            }
            #pragma unroll
            for (int o = 16; o; o >>= 1) {
                dot += __shfl_xor_sync(0xffffffffu, dot, o);
                ss  += __shfl_xor_sync(0xffffffffu, ss,  o);
            }
            val = dot / fmaxf(sqrtf(ss), 1e-12f);
        }
        if (lane == 0) rv[c] = val;
    }
    __syncthreads();

    if (tid == 0) {
        bool used[CAND];
        #pragma unroll
        for (int i = 0; i < CAND; i++) used[i] = false;
        for (int j = 0; j < k; j++) {
            int best = -1; float bvv = -3.4e38f;
            for (int i = 0; i < CAND; i++) {
                if (used[i]) continue;
                if (best < 0 || rv[i] > bvv ||
                    (rv[i] == bvv && sid[i] < sid[best])) { bvv = rv[i]; best = i; }
            }
            used[best] = true;
            out[q * k + j]          = bvv;
            out[NQ * k + q * k + j] = (float)sid[best];
        }
    }
}

// ---------------- launch -----------------------------------------------------
extern "C" void kernel_launch(void* const* d_in, const int* in_sizes, int n_in,
                              void* d_out, int out_size) {
    const float* query = (const float*)d_in[0];
    const float* bank  = (const float*)d_in[1];
    const int nrows = in_sizes[1] / KDIM;
    const int k = out_size / (2 * NQ);

    cudaFuncSetAttribute(score_kernel, cudaFuncAttributeMaxDynamicSharedMemorySize, SCORE_SMEM);

    norm_q_kernel<<<NQ, 256>>>(query);

    const int ntiles = (nrows + TILE_M - 1) / TILE_M;
    score_kernel<<<ntiles, 256, SCORE_SMEM>>>(bank, nrows);

    topk_kernel<<<dim3(NSEG, NQ), 256>>>(nrows);

    final_kernel<<<NQ, 256>>>(bank, (float*)d_out, nrows, k);
}

// round 12
// speedup vs baseline: 1.5062x; 1.5062x over previous
#include <cuda_runtime.h>
#include <cuda_bf16.h>
#include <math.h>

// ---------------- problem constants ------------------------------------------
#define NQ      64
#define KDIM    768
#define TILE_M  128                 // bank rows per CTA tile
#define CHUNK_K 64                  // K elems per chunk (bf16 row = 128 B)
#define NCHUNK  (KDIM / CHUNK_K)    // 12
#define MAXROWS 500000
#define NSEG    8                   // top-k segments per query
#define SEGK    16                  // candidates kept per (q, segment)
#define CAND    32                  // candidates exactly rescored per query
#define TB_PAD  136                 // transpose buffer row pitch (bf16 elems)
#define NTHREADS 512                // 16 warps -> 4 warps per SMSP

// ---------------- smem layout (score kernel) ---------------------------------
#define SM_INVN 0                                   // float[128]
#define SM_Q    1024                                // 12 chunks x 64 q x 128 B = 98304
#define SM_B0   (SM_Q + NCHUNK * 64 * 128)          // 99328: B buf 0 (16 KB)
#define SM_B1   (SM_B0 + TILE_M * 128)              // 115712: B buf 1 (16 KB)
#define SCORE_SMEM (SM_B1 + TILE_M * 128)           // 132096 (fits 227 KB carveout)

// ---------------- device scratch (allocation-free rule) ----------------------
__device__ __align__(16) float         g_qn   [NQ * KDIM];            // fp32 normalized queries
__device__ __align__(16) __nv_bfloat16 g_qnb  [NQ * KDIM];            // bf16 copy
__device__ __align__(16) __nv_bfloat16 g_simsb[(size_t)NQ * MAXROWS]; // 64 MB bf16 sims
__device__ float g_segv[NQ * NSEG * SEGK];
__device__ int   g_segi[NQ * NSEG * SEGK];

// ---------------- kernel 1: normalize queries --------------------------------
__global__ void norm_q_kernel(const float* __restrict__ q) {
    __shared__ float red[256];
    int qi = blockIdx.x, tid = threadIdx.x;
    const float* qr = q + qi * KDIM;
    float v0 = qr[tid], v1 = qr[tid + 256], v2 = qr[tid + 512];
    red[tid] = v0 * v0 + v1 * v1 + v2 * v2;
    __syncthreads();
    for (int st = 128; st > 0; st >>= 1) {
        if (tid < st) red[tid] += red[tid + st];
        __syncthreads();
    }
    float inv = 1.0f / fmaxf(sqrtf(red[0]), 1e-12f);
    float o0 = v0 * inv, o1 = v1 * inv, o2 = v2 * inv;
    g_qn[qi * KDIM + tid      ] = o0;
    g_qn[qi * KDIM + tid + 256] = o1;
    g_qn[qi * KDIM + tid + 512] = o2;
    g_qnb[qi * KDIM + tid      ] = __float2bfloat16(o0);
    g_qnb[qi * KDIM + tid + 256] = __float2bfloat16(o1);
    g_qnb[qi * KDIM + tid + 512] = __float2bfloat16(o2);
}

// ---------------- kernel 2: mma.sync score (16 warps, double-buffered B) -----
__device__ __forceinline__ void ld_chunk(float4 (&f)[4], const float* const (&rp)[4],
                                         const bool (&vld)[4], int c) {
    #pragma unroll
    for (int p = 0; p < 4; p++) {
        if (vld[p]) f[p] = *(const float4*)(rp[p] + c * CHUNK_K);
        else        f[p] = make_float4(0.f, 0.f, 0.f, 0.f);
    }
}

__device__ __forceinline__ void ldsm_x4(unsigned& r0, unsigned& r1, unsigned& r2,
                                        unsigned& r3, unsigned addr) {
    asm volatile("ldmatrix.sync.aligned.m8n8.x4.shared.b16 {%0,%1,%2,%3}, [%4];"
                 : "=r"(r0), "=r"(r1), "=r"(r2), "=r"(r3) : "r"(addr));
}

__device__ __forceinline__ unsigned s2u(const void* p) {
    unsigned a;
    asm("{ .reg .u64 t; cvta.to.shared.u64 t, %1; cvt.u32.u64 %0, t; }" : "=r"(a) : "l"(p));
    return a;
}

__global__ __launch_bounds__(NTHREADS, 1)
void score_kernel(const float* __restrict__ bank, int nrows) {
    extern __shared__ char smem[];
    const unsigned sbase = s2u(smem);
    const int tid = threadIdx.x, warp = tid >> 5, lane = tid & 31;
    const int lr = lane >> 4, lc = lane & 15;

    // ---- global load mapping: 16 lanes per row, 4 rows per thread -------------
    int rloc[4]; const float* rp[4]; bool vld[4]; float ssq[4];
    #pragma unroll
    for (int p = 0; p < 4; p++) {
        int r = p * 32 + warp * 2 + lr;
        rloc[p] = r;
        long long grow = (long long)blockIdx.x * TILE_M + r;
        vld[p] = grow < (long long)nrows;
        rp[p]  = bank + grow * (long long)KDIM + lc * 4;
        ssq[p] = 0.f;
    }
    const int scol = (lc * 8) ^ (((warp * 2 + lr) & 7) << 4);  // row&7 is p-invariant

    // ---- stage all queries: [chunk][64 q][128 B], XOR-swizzled ----------------
    for (int i = tid; i < NQ * KDIM / 4; i += NTHREADS) {
        int qi  = i / 192;
        int rem = i - qi * 192;
        int c   = rem >> 4;
        int k4  = rem & 15;
        uint2 v = ((const uint2*)g_qnb)[i];
        *(uint2*)(smem + SM_Q + c * 8192 + qi * 128 + ((k4 * 8) ^ ((qi & 7) << 4))) = v;
    }

    // ---- mma thread constants: warp = (qstrip 0-3, nstrip 0-3) ----------------
    const int qbase = (warp & 3) * 16;          // m (query) strip
    const int nbase = (warp >> 2) * 32;         // n (bank row) strip
    const int arow  = qbase + ((lane >> 3) & 1) * 8 + (lane & 7);
    const int axtr  = (lane >> 4) * 16;
    const int brow0 = nbase + ((lane >> 4) & 1) * 8 + (lane & 7);   // + pair*16
    const int bxtr  = ((lane >> 3) & 1) * 16;
    const int lsw   = (lane & 7) << 4;

    float acc[4][4];
    #pragma unroll
    for (int i = 0; i < 4; i++)
        #pragma unroll
        for (int j = 0; j < 4; j++) acc[i][j] = 0.f;

    float4 f[4];
    ld_chunk(f, rp, vld, 0);           // prologue: chunk 0 in flight

    for (int c = 0; c < NCHUNK; c++) {
        const unsigned bb = sbase + ((c & 1) ? SM_B1 : SM_B0);
        // convert + STS chunk c into buffer c&1
        #pragma unroll
        for (int p = 0; p < 4; p++) {
            float4 fv = f[p];
            ssq[p] += fv.x * fv.x + fv.y * fv.y + fv.z * fv.z + fv.w * fv.w;
            __nv_bfloat162 p0 = __floats2bfloat162_rn(fv.x, fv.y);
            __nv_bfloat162 p1 = __floats2bfloat162_rn(fv.z, fv.w);
            uint2 u;
            u.x = *(unsigned*)&p0;
            u.y = *(unsigned*)&p1;
            *(uint2*)(smem + ((c & 1) ? SM_B1 : SM_B0) + rloc[p] * 128 + scol) = u;
        }
        __syncthreads();   // single sync: STS(c) visible; also guarantees all
                           // warps finished mma(c-1) [program order], so the
                           // upcoming STS(c+1) into the other buffer is safe.

        // next chunk's loads issued before mma work (latency hidden behind mma)
        if (c + 1 < NCHUNK) ld_chunk(f, rp, vld, c + 1);

        // mma over chunk c: 4 k16 steps x 4 ntiles
        const unsigned qb = sbase + SM_Q + c * 8192;
        #pragma unroll
        for (int kk = 0; kk < 4; kk++) {
            unsigned a0, a1, a2, a3;
            ldsm_x4(a0, a1, a2, a3,
                    qb + arow * 128 + ((kk * 32 + axtr) ^ lsw));
            #pragma unroll
            for (int pair = 0; pair < 2; pair++) {
                unsigned b0, b1, b2, b3;
                ldsm_x4(b0, b1, b2, b3,
                        bb + (brow0 + pair * 16) * 128 + ((kk * 32 + bxtr) ^ lsw));
                asm volatile(
                    "mma.sync.aligned.m16n8k16.row.col.f32.bf16.bf16.f32 "
                    "{%0,%1,%2,%3}, {%4,%5,%6,%7}, {%8,%9}, {%0,%1,%2,%3};\n"
                    : "+f"(acc[pair*2][0]), "+f"(acc[pair*2][1]),
                      "+f"(acc[pair*2][2]), "+f"(acc[pair*2][3])
                    : "r"(a0), "r"(a1), "r"(a2), "r"(a3), "r"(b0), "r"(b1));
                asm volatile(
                    "mma.sync.aligned.m16n8k16.row.col.f32.bf16.bf16.f32 "
                    "{%0,%1,%2,%3}, {%4,%5,%6,%7}, {%8,%9}, {%0,%1,%2,%3};\n"
                    : "+f"(acc[pair*2+1][0]), "+f"(acc[pair*2+1][1]),
                      "+f"(acc[pair*2+1][2]), "+f"(acc[pair*2+1][3])
                    : "r"(a0), "r"(a1), "r"(a2), "r"(a3), "r"(b2), "r"(b3));
            }
        }
    }

    // ---- row inverse norms (16 lanes share a row) -----------------------------
    float* invn = (float*)(smem + SM_INVN);
    #pragma unroll
    for (int p = 0; p < 4; p++) {
        float s = ssq[p];
        s += __shfl_xor_sync(0xffffffffu, s, 1);
        s += __shfl_xor_sync(0xffffffffu, s, 2);
        s += __shfl_xor_sync(0xffffffffu, s, 4);
        s += __shfl_xor_sync(0xffffffffu, s, 8);
        if (lc == 0) invn[rloc[p]] = 1.0f / fmaxf(sqrtf(s), 1e-12f);
    }
    __syncthreads();   // invn ready; all mma done (last chunk's mma precedes this)

    // ---- epilogue 1: regs -> smem transpose buffer [q][TB_PAD] bf16 -----------
    // (reuses B buffer 0 region; 17408 B <= 32 KB)
    {
        __nv_bfloat16* tb = (__nv_bfloat16*)(smem + SM_B0);
        const int q0 = qbase + (lane >> 2);
        #pragma unroll
        for (int nt = 0; nt < 4; nt++) {
            const int r0 = nbase + nt * 8 + (lane & 3) * 2;
            const float i0 = invn[r0], i1 = invn[r0 + 1];
            __nv_bfloat162 v01 = __floats2bfloat162_rn(acc[nt][0] * i0, acc[nt][1] * i1);
            __nv_bfloat162 v23 = __floats2bfloat162_rn(acc[nt][2] * i0, acc[nt][3] * i1);
            *(__nv_bfloat162*)&tb[ q0      * TB_PAD + r0] = v01;
            *(__nv_bfloat162*)&tb[(q0 + 8) * TB_PAD + r0] = v23;
        }
    }
    __syncthreads();

    // ---- epilogue 2: coalesced vectorized sims store --------------------------
    {
        const int q = tid >> 3, seg = tid & 7;      // 8 segs x 16 rows
        const long long tb0 = (long long)blockIdx.x * TILE_M;
        const __nv_bfloat16* tb = (const __nv_bfloat16*)(smem + SM_B0);
        __nv_bfloat16* dst = g_simsb + (size_t)q * nrows;
        if ((nrows & 7) == 0) {
            #pragma unroll
            for (int i = 0; i < 2; i++) {
                long long g0 = tb0 + seg * 16 + i * 8;
                if (g0 + 8 <= (long long)nrows) {
                    uint4 v = *(const uint4*)(smem + SM_B0 + q * (TB_PAD * 2) + seg * 32 + i * 16);
                    *(uint4*)(dst + g0) = v;
                } else {
                    for (int e = 0; e < 8 && g0 + e < (long long)nrows; e++)
                        dst[g0 + e] = tb[q * TB_PAD + seg * 16 + i * 8 + e];
                }
            }
        } else {
            for (int i = 0; i < 16; i++) {
                long long g0 = tb0 + seg * 16 + i;
                if (g0 < (long long)nrows) dst[g0] = tb[q * TB_PAD + seg * 16 + i];
            }
        }
    }
}

// ---------------- kernel 3: segmented top-16 screening -----------------------
__device__ __forceinline__ void tk_insert(float (&v)[SEGK], int (&id)[SEGK],
                                          float nv, int ni) {
    if (nv <= v[SEGK - 1]) return;
    int j = SEGK - 1;
    while (j > 0 && nv > v[j - 1]) { v[j] = v[j - 1]; id[j] = id[j - 1]; j--; }
    v[j] = nv; id[j] = ni;
}

__global__ __launch_bounds__(256, 1) void topk_kernel(int nrows) {
    __shared__ float sv[256 * SEGK];
    __shared__ int   si[256 * SEGK];
    const int seg = blockIdx.x, q = blockIdx.y, tid = threadIdx.x;
    const int len  = ((nrows + NSEG - 1) / NSEG + 3) & ~3;
    const int base = seg * len;
    const int end  = min(base + len, nrows);
    const __nv_bfloat16* s = g_simsb + (size_t)q * nrows;

    float vals[SEGK]; int ids[SEGK];
    #pragma unroll
    for (int i = 0; i < SEGK; i++) { vals[i] = -3.4e38f; ids[i] = 0x7fffffff; }

    if ((nrows & 3) == 0 && base < end) {
        const uint2* s4 = (const uint2*)s;
        for (int i = (base >> 2) + tid; i < (end >> 2); i += 256) {
            uint2 u = s4[i];
            __nv_bfloat162 p0 = *(__nv_bfloat162*)&u.x;
            __nv_bfloat162 p1 = *(__nv_bfloat162*)&u.y;
            int bi = i << 2;
            tk_insert(vals, ids, __low2float(p0),  bi);
            tk_insert(vals, ids, __high2float(p0), bi + 1);
            tk_insert(vals, ids, __low2float(p1),  bi + 2);
            tk_insert(vals, ids, __high2float(p1), bi + 3);
        }
    } else {
        for (int i = base + tid; i < end; i += 256)
            tk_insert(vals, ids, __bfloat162float(s[i]), i);
    }

    #pragma unroll
    for (int i = 0; i < SEGK; i++) { sv[tid * SEGK + i] = vals[i]; si[tid * SEGK + i] = ids[i]; }
    __syncthreads();

    for (int st = 128; st > 0; st >>= 1) {
        if (tid < st) {
            const int ao = tid * SEGK, bo = (tid + st) * SEGK;
            float ov[SEGK]; int oi[SEGK];
            int ia = 0, ib = 0;
            #pragma unroll
            for (int o = 0; o < SEGK; o++) {
                float va = (ia < SEGK) ? sv[ao + ia] : -3.4e38f;
                float vb = (ib < SEGK) ? sv[bo + ib] : -3.4e38f;
                bool takeA;
                if (va > vb) takeA = true;
                else if (va < vb) takeA = false;
                else takeA = (si[ao + min(ia, SEGK - 1)] <= si[bo + min(ib, SEGK - 1)]);
                if (takeA) { ov[o] = va; oi[o] = si[ao + min(ia, SEGK - 1)]; ia++; }
                else       { ov[o] = vb; oi[o] = si[bo + min(ib, SEGK - 1)]; ib++; }
            }
            #pragma unroll
            for (int o = 0; o < SEGK; o++) { sv[ao + o] = ov[o]; si[ao + o] = oi[o]; }
        }
        __syncthreads();
    }

    if (tid == 0) {
        #pragma unroll
        for (int i = 0; i < SEGK; i++) {
            g_segv[(q * NSEG + seg) * SEGK + i] = sv[i];
            g_segi[(q * NSEG + seg) * SEGK + i] = si[i];
        }
    }
}

// ---------------- kernel 4: merge + exact fp32 rescore + final top-k ---------
__global__ __launch_bounds__(256, 1)
void final_kernel(const float* __restrict__ bank, float* __restrict__ out,
                  int nrows, int k) {
    __shared__ float cv[NSEG * SEGK];
    __shared__ int   ci[NSEG * SEGK];
    __shared__ float sv[CAND];
    __shared__ int   sid[CAND];
    __shared__ float rv[CAND];
    const int q = blockIdx.x, tid = threadIdx.x;
    const int lane = tid & 31, warp = tid >> 5;

    if (tid < NSEG * SEGK) {
        cv[tid] = g_segv[q * NSEG * SEGK + tid];
        ci[tid] = g_segi[q * NSEG * SEGK + tid];
    }
    __syncthreads();

    if (tid == 0) {
        float bv[CAND]; int bi[CAND];
        #pragma unroll
        for (int i = 0; i < CAND; i++) { bv[i] = -3.4e38f; bi[i] = 0x7fffffff; }
        for (int i = 0; i < NSEG * SEGK; i++) {
            float v = cv[i]; int id = ci[i];
            float lv = bv[CAND - 1]; int li = bi[CAND - 1];
            if (v < lv || (v == lv && id >= li)) continue;
            int j = CAND - 1;
            while (j > 0 && (v > bv[j - 1] || (v == bv[j - 1] && id < bi[j - 1]))) {
                bv[j] = bv[j - 1]; bi[j] = bi[j - 1]; j--;
            }
            bv[j] = v; bi[j] = id;
        }
        #pragma unroll
        for (int i = 0; i < CAND; i++) { sv[i] = bv[i]; sid[i] = bi[i]; }
    }
    __syncthreads();

    for (int c = warp; c < CAND; c += 8) {
        const int id = sid[c];
        float val = -3.4e38f;
        if (id < nrows) {
            const float4* b4 = (const float4*)(bank + (long long)id * KDIM);
            const float4* q4 = (const float4*)(g_qn + q * KDIM);
            float dot = 0.f, ss = 0.f;
            #pragma unroll
            for (int i = 0; i < 6; i++) {
                float4 bb = b4[lane + i * 32];
                float4 qq = q4[lane + i * 32];
                dot = fmaf(qq.x, bb.x, fmaf(qq.y, bb.y, fmaf(qq.z, bb.z, fmaf(qq.w, bb.w, dot))));
                ss  = fmaf(bb.x, bb.x, fmaf(bb.y, bb.y, fmaf(bb.z, bb.z, fmaf(bb.w, bb.w, ss))));
            }
            #pragma unroll
            for (int o = 16; o; o >>= 1) {
                dot += __shfl_xor_sync(0xffffffffu, dot, o);
                ss  += __shfl_xor_sync(0xffffffffu, ss,  o);
            }
            val = dot / fmaxf(sqrtf(ss), 1e-12f);
        }
        if (lane == 0) rv[c] = val;
    }
    __syncthreads();

    if (tid == 0) {
        bool used[CAND];
        #pragma unroll
        for (int i = 0; i < CAND; i++) used[i] = false;
        for (int j = 0; j < k; j++) {
            int best = -1; float bvv = -3.4e38f;
            for (int i = 0; i < CAND; i++) {
                if (used[i]) continue;
                if (best < 0 || rv[i] > bvv ||
                    (rv[i] == bvv && sid[i] < sid[best])) { bvv = rv[i]; best = i; }
            }
            used[best] = true;
            out[q * k + j]          = bvv;
            out[NQ * k + q * k + j] = (float)sid[best];
        }
    }
}

// ---------------- launch -----------------------------------------------------
extern "C" void kernel_launch(void* const* d_in, const int* in_sizes, int n_in,
                              void* d_out, int out_size) {
    const float* query = (const float*)d_in[0];
    const float* bank  = (const float*)d_in[1];
    const int nrows = in_sizes[1] / KDIM;
    const int k = out_size / (2 * NQ);

    cudaFuncSetAttribute(score_kernel, cudaFuncAttributeMaxDynamicSharedMemorySize, SCORE_SMEM);

    norm_q_kernel<<<NQ, 256>>>(query);

    const int ntiles = (nrows + TILE_M - 1) / TILE_M;
    score_kernel<<<ntiles, NTHREADS, SCORE_SMEM>>>(bank, nrows);

    topk_kernel<<<dim3(NSEG, NQ), 256>>>(nrows);

    final_kernel<<<NQ, 256>>>(bank, (float*)d_out, nrows, k);
}